// round 2
// baseline (speedup 1.0000x reference)
#include <cuda_runtime.h>

// Problem constants
#define BB 8
#define CC 128
#define HH 128
#define WW 128
#define KWID 9
#define PWID 4

// Workspaces: (B, S, P, C) with C contiguous. 64 MB each.
__device__ float g_ws1[(size_t)BB * HH * WW * CC];
__device__ float g_ws2[(size_t)BB * HH * WW * CC];

// ---------------------------------------------------------------------------
// Step kernel: one directional-scan step.
//   y[b, s_cur, p, oc] += relu( sum_{kw,ic} y[b, s_prev, p+kw-4, ic] * W9[kw,ic,oc] )
// Layout of y: (B=8, S=128, P=128, C=128), C contiguous. Zero padding on p.
// WS selects workspace (0 -> g_ws1, 1 -> g_ws2) so no host-side symbol lookup
// is needed (keeps kernel_launch trivially graph-capturable).
// ---------------------------------------------------------------------------
#define MT 16   // positions per block
#define NT 32   // out-channels per block

template <int WS>
__global__ void step_kernel(const float* __restrict__ W9, int s_cur, int s_prev)
{
    float* y = WS ? g_ws2 : g_ws1;

    // A window: positions [p0-4, p0+MT+4), all 128 input channels.
    // Row stride padded to 132 floats: rows map to distinct banks for the
    // broadcast A reads (4 distinct rows per warp), and 132*4 B is 16B aligned.
    __shared__ __align__(16) float As[MT + 8][132];
    __shared__ __align__(16) float Bs[128 * NT];

    const int tx  = threadIdx.x;          // 0..7   -> oc group (4 each)
    const int ty  = threadIdx.y;          // 0..15  -> position m
    const int tid = ty * 8 + tx;          // 0..127
    const int p0  = blockIdx.x * MT;
    const int oc0 = blockIdx.y * NT;
    const int b   = blockIdx.z;

    const float* prev = y + (((size_t)b * 128 + s_prev) * 128) * 128;

    // Stage A window (zero-padded outside [0,128)).
    for (int t = tid; t < (MT + 8) * 32; t += 128) {
        int r  = t >> 5;       // 0..23 : position row, p = p0 - 4 + r
        int j  = t & 31;       // float4 within row
        int gp = p0 - 4 + r;
        float4 v = make_float4(0.f, 0.f, 0.f, 0.f);
        if (gp >= 0 && gp < 128)
            v = *(const float4*)(prev + (size_t)gp * 128 + j * 4);
        *(float4*)&As[r][j * 4] = v;
    }

    // Two packed f32x2 accumulators = 4 fp32 outputs per thread.
    unsigned long long acc01 = 0ull, acc23 = 0ull;   // bit pattern == {0.f,0.f}
    const int ocl = tx * 4;

    for (int kw = 0; kw < KWID; ++kw) {
        __syncthreads();
        // Stage weights for this kw: Bs[ic][0..NT) = W9[kw, ic, oc0..oc0+NT)
        const float* wsrc = W9 + ((size_t)kw * 128) * 128 + oc0;
        for (int t = tid; t < 128 * (NT / 4); t += 128) {
            int ic = t >> 3;   // NT/4 == 8 float4 per ic row
            int j  = t & 7;
            *(float4*)&Bs[ic * NT + j * 4] = *(const float4*)(wsrc + (size_t)ic * 128 + j * 4);
        }
        __syncthreads();

        const float* Arow = &As[ty + kw][0];   // input position = p0+ty + kw - 4
        const float* Bp   = &Bs[ocl];
        #pragma unroll 8
        for (int ic = 0; ic < 128; ++ic) {
            float a = Arow[ic];
            unsigned long long a2;
            asm("mov.b64 %0, {%1, %1};" : "=l"(a2) : "f"(a));
            unsigned long long b01 = *(const unsigned long long*)(Bp + ic * NT);
            unsigned long long b23 = *(const unsigned long long*)(Bp + ic * NT + 2);
            asm("fma.rn.f32x2 %0, %1, %2, %0;" : "+l"(acc01) : "l"(a2), "l"(b01));
            asm("fma.rn.f32x2 %0, %1, %2, %0;" : "+l"(acc23) : "l"(a2), "l"(b23));
        }
    }

    float r0, r1, r2, r3;
    asm("mov.b64 {%0, %1}, %2;" : "=f"(r0), "=f"(r1) : "l"(acc01));
    asm("mov.b64 {%0, %1}, %2;" : "=f"(r2), "=f"(r3) : "l"(acc23));

    float* dst = y + ((((size_t)b * 128 + s_cur) * 128 + (p0 + ty)) * 128) + oc0 + ocl;
    float4 cur = *(float4*)dst;
    cur.x += fmaxf(r0, 0.f);
    cur.y += fmaxf(r1, 0.f);
    cur.z += fmaxf(r2, 0.f);
    cur.w += fmaxf(r3, 0.f);
    *(float4*)dst = cur;
}

// ---------------------------------------------------------------------------
// Transposes
// ---------------------------------------------------------------------------

// x (B,C,H,W) -> g_ws1 (B,H,W,C). Per (b,h) slab: (C,W) -> (W,C) transpose.
__global__ void t_in(const float* __restrict__ x)
{
    __shared__ float t[32][33];
    const int bh = blockIdx.z;
    const int b = bh >> 7, h = bh & 127;
    const int w0 = blockIdx.x * 32;
    const int c0 = blockIdx.y * 32;
    const int tx = threadIdx.x, ty = threadIdx.y;  // 32 x 8

    const float* src = x + (((size_t)b * 128 + c0) * 128 + h) * 128 + w0;
    #pragma unroll
    for (int i = 0; i < 4; ++i) {
        int c = ty * 4 + i;
        t[c][tx] = src[(size_t)c * 128 * 128 + tx];       // coalesced over w
    }
    __syncthreads();
    float* d = g_ws1 + (((size_t)b * 128 + h) * 128 + w0) * 128 + c0;
    #pragma unroll
    for (int i = 0; i < 4; ++i) {
        int w = ty * 4 + i;
        d[(size_t)w * 128 + tx] = t[tx][w];               // coalesced over c
    }
}

// g_ws1 (B,H,W,C) -> g_ws2 (B,W,H,C): swap H/W, C rows stay contiguous.
__global__ void t_mid()
{
    const int b = blockIdx.z;
    const int h = blockIdx.y;
    const int w = blockIdx.x * blockDim.y + threadIdx.y;
    const int c4 = threadIdx.x;  // 0..31 (float4 index)
    const float4* s = (const float4*)(g_ws1 + (((size_t)b * 128 + h) * 128 + w) * 128);
    float4* d = (float4*)(g_ws2 + (((size_t)b * 128 + w) * 128 + h) * 128);
    d[c4] = s[c4];
}

// g_ws2 (B,W,H,C) -> out (B,C,H,W). Per (b,h) slab: (W,C) -> (C,W) transpose.
__global__ void t_out(float* __restrict__ out)
{
    __shared__ float t[32][33];
    const int bh = blockIdx.z;
    const int b = bh >> 7, h = bh & 127;
    const int w0 = blockIdx.x * 32;
    const int c0 = blockIdx.y * 32;
    const int tx = threadIdx.x, ty = threadIdx.y;  // 32 x 8

    const float* src = g_ws2 + (((size_t)b * 128 + w0) * 128 + h) * 128 + c0;
    #pragma unroll
    for (int i = 0; i < 4; ++i) {
        int w = ty * 4 + i;
        t[w][tx] = src[(size_t)w * 128 * 128 + tx];       // coalesced over c
    }
    __syncthreads();
    float* d = out + (((size_t)b * 128 + c0) * 128 + h) * 128 + w0;
    #pragma unroll
    for (int i = 0; i < 4; ++i) {
        int c = ty * 4 + i;
        d[(size_t)c * 128 * 128 + tx] = t[tx][c];         // coalesced over w
    }
}

// ---------------------------------------------------------------------------
// Launch
// ---------------------------------------------------------------------------
extern "C" void kernel_launch(void* const* d_in, const int* in_sizes, int n_in,
                              void* d_out, int out_size)
{
    const float* x    = (const float*)d_in[0];
    const float* k_td = (const float*)d_in[1];
    const float* k_dt = (const float*)d_in[2];
    const float* k_lr = (const float*)d_in[3];
    const float* k_rl = (const float*)d_in[4];
    float* out = (float*)d_out;

    const dim3 tb(32, 8);
    const dim3 tg(4, 4, BB * HH);
    const dim3 sb(8, 16);
    const dim3 sg(WW / MT, CC / NT, BB);   // (8, 4, 8) = 256 blocks

    // (B,C,H,W) -> ws1 (B,H,W,C)
    t_in<<<tg, tb>>>(x);

    // top-down then bottom-up scans over H (conv over W)
    for (int s = 1; s < HH; ++s)
        step_kernel<0><<<sg, sb>>>(k_td, s, s - 1);
    for (int s = HH - 2; s >= 0; --s)
        step_kernel<0><<<sg, sb>>>(k_dt, s, s + 1);

    // ws1 (B,H,W,C) -> ws2 (B,W,H,C)
    t_mid<<<dim3(32, 128, BB), dim3(32, 4)>>>();

    // left-right then right-left scans over W (conv over H)
    for (int s = 1; s < WW; ++s)
        step_kernel<1><<<sg, sb>>>(k_lr, s, s - 1);
    for (int s = WW - 2; s >= 0; --s)
        step_kernel<1><<<sg, sb>>>(k_rl, s, s + 1);

    // ws2 (B,W,H,C) -> out (B,C,H,W)
    t_out<<<tg, tb>>>(out);
}

// round 3
// speedup vs baseline: 2.1975x; 2.1975x over previous
#include <cuda_runtime.h>

#define BB 8
#define HH 128
#define WW 128

// Workspaces: (B, S, P, C) with C contiguous. 64 MB each.
__device__ float g_ws1[(size_t)BB * HH * WW * 128];
__device__ float g_ws2[(size_t)BB * HH * WW * 128];

typedef unsigned long long ull;

__device__ __forceinline__ void cp_async16(void* sdst, const void* gsrc) {
    unsigned s = (unsigned)__cvta_generic_to_shared(sdst);
    asm volatile("cp.async.ca.shared.global [%0], [%1], 16;\n" :: "r"(s), "l"(gsrc));
}

#define MT 32      // positions per block
#define NT 16      // out-channels per block
#define AROW 129   // A row stride in floats (odd => conflict-free strided lane access)
#define NROWS 40   // MT + 8 halo rows

// ---------------------------------------------------------------------------
// One directional-scan step:
//   y[b,s_cur,p,oc] += relu( sum_{kw,ic} y[b,s_prev,p+kw-4,ic] * W9[kw,ic,oc] )
// Block: 256 threads = 8 warps. Warp w handles ic in [16w, 16w+16) for ALL
// 512 outputs of the block (in-block K-split); smem reduction at the end.
// Per-thread micro-tile: 2 positions x 8 oc, f32x2 packed accumulators.
// ---------------------------------------------------------------------------
template <int WS>
__global__ __launch_bounds__(256) void step_kernel(const float* __restrict__ W9,
                                                   int s_cur, int s_prev)
{
    float* y = WS ? g_ws2 : g_ws1;

    __shared__ __align__(16) float Bs[2][128 * NT];   // double-buffered W9[kw] slice
    __shared__ __align__(16) float As[NROWS * AROW];  // prev-row window (Rs aliases)

    const int tid  = threadIdx.x;
    const int wid  = tid >> 5;       // 0..7  -> ic slice
    const int lane = tid & 31;
    const int og   = lane & 1;       // oc group (8 each)
    const int pg   = lane >> 1;      // position pair 0..15
    const int ic0  = wid * 16;
    const int p0   = blockIdx.x * MT;
    const int oc0  = blockIdx.y * NT;
    const int b    = blockIdx.z;

    const float* prev = y + (((size_t)b * 128 + s_prev) * 128) * 128;

    // ---- Stage A window (rows p0-4 .. p0+35, zero-padded) ----
    for (int t = tid; t < NROWS * 32; t += 256) {
        int r = t >> 5, j = t & 31;
        int gp = p0 - 4 + r;
        float4 v = make_float4(0.f, 0.f, 0.f, 0.f);
        if (gp >= 0 && gp < 128) v = *(const float4*)(prev + (size_t)gp * 128 + j * 4);
        float* d = &As[r * AROW + j * 4];
        d[0] = v.x; d[1] = v.y; d[2] = v.z; d[3] = v.w;
    }

    // ---- Stage B[kw=0] async (128 ic x 16 oc = 8KB) ----
    const float* wbase = W9 + oc0;
    {
        int r = tid >> 2, j = (tid & 3) * 4;
        cp_async16(&Bs[0][r * NT + j],        wbase + (size_t)r * 128 + j);
        cp_async16(&Bs[0][(r + 64) * NT + j], wbase + (size_t)(r + 64) * 128 + j);
    }
    asm volatile("cp.async.commit_group;\n");
    asm volatile("cp.async.wait_group 0;\n");
    __syncthreads();

    ull acc[2][4];
    #pragma unroll
    for (int p = 0; p < 2; ++p)
        #pragma unroll
        for (int q = 0; q < 4; ++q) acc[p][q] = 0ull;

    for (int kw = 0; kw < 9; ++kw) {
        // Prefetch next kw's weights into the other buffer.
        if (kw < 8) {
            const float* wk = wbase + (size_t)(kw + 1) * 128 * 128;
            float* bd = Bs[(kw + 1) & 1];
            int r = tid >> 2, j = (tid & 3) * 4;
            cp_async16(&bd[r * NT + j],        wk + (size_t)r * 128 + j);
            cp_async16(&bd[(r + 64) * NT + j], wk + (size_t)(r + 64) * 128 + j);
            asm volatile("cp.async.commit_group;\n");
        }

        const float* Ar = &As[(2 * pg + kw) * AROW + ic0];
        const float* Bp = &Bs[kw & 1][ic0 * NT + 8 * og];

        #pragma unroll
        for (int i = 0; i < 16; ++i) {
            float a0 = Ar[i];
            float a1 = Ar[i + AROW];
            ull a0d, a1d;
            asm("mov.b64 %0, {%1, %1};" : "=l"(a0d) : "f"(a0));
            asm("mov.b64 %0, {%1, %1};" : "=l"(a1d) : "f"(a1));
            const ulonglong2* bp = (const ulonglong2*)(Bp + i * NT);
            ulonglong2 bx = bp[0];   // oc +0..3 as two f32x2
            ulonglong2 by = bp[1];   // oc +4..7
            asm("fma.rn.f32x2 %0, %1, %2, %0;" : "+l"(acc[0][0]) : "l"(a0d), "l"(bx.x));
            asm("fma.rn.f32x2 %0, %1, %2, %0;" : "+l"(acc[0][1]) : "l"(a0d), "l"(bx.y));
            asm("fma.rn.f32x2 %0, %1, %2, %0;" : "+l"(acc[0][2]) : "l"(a0d), "l"(by.x));
            asm("fma.rn.f32x2 %0, %1, %2, %0;" : "+l"(acc[0][3]) : "l"(a0d), "l"(by.y));
            asm("fma.rn.f32x2 %0, %1, %2, %0;" : "+l"(acc[1][0]) : "l"(a1d), "l"(bx.x));
            asm("fma.rn.f32x2 %0, %1, %2, %0;" : "+l"(acc[1][1]) : "l"(a1d), "l"(bx.y));
            asm("fma.rn.f32x2 %0, %1, %2, %0;" : "+l"(acc[1][2]) : "l"(a1d), "l"(by.x));
            asm("fma.rn.f32x2 %0, %1, %2, %0;" : "+l"(acc[1][3]) : "l"(a1d), "l"(by.y));
        }

        if (kw < 8) {
            asm volatile("cp.async.wait_group 0;\n");
            __syncthreads();
        }
    }
    __syncthreads();   // all warps done reading As before Rs alias-writes

    // ---- Cross-warp reduction through smem (Rs aliases As) ----
    float* Rs = As;    // 8 * 512 floats = 4096 <= 5160 available
    {
        int base = wid * 512 + (2 * pg) * 16 + 8 * og;
        #pragma unroll
        for (int q = 0; q < 4; ++q) {
            float lo, hi;
            asm("mov.b64 {%0, %1}, %2;" : "=f"(lo), "=f"(hi) : "l"(acc[0][q]));
            Rs[base + 2 * q]          = lo;
            Rs[base + 2 * q + 1]      = hi;
            asm("mov.b64 {%0, %1}, %2;" : "=f"(lo), "=f"(hi) : "l"(acc[1][q]));
            Rs[base + 16 + 2 * q]     = lo;
            Rs[base + 16 + 2 * q + 1] = hi;
        }
    }
    __syncthreads();

    // ---- Final sum, relu, RMW store: thread t owns outputs 2t, 2t+1 ----
    {
        int o   = 2 * tid;
        int pos = o >> 4;        // 0..31
        int oc  = o & 15;        // even
        float s0 = 0.f, s1 = 0.f;
        #pragma unroll
        for (int w = 0; w < 8; ++w) {
            s0 += Rs[w * 512 + pos * 16 + oc];
            s1 += Rs[w * 512 + pos * 16 + oc + 1];
        }
        float* dst = y + (((size_t)b * 128 + s_cur) * 128 + (p0 + pos)) * 128 + oc0 + oc;
        float2 cur = *(float2*)dst;
        cur.x += fmaxf(s0, 0.f);
        cur.y += fmaxf(s1, 0.f);
        *(float2*)dst = cur;
    }
}

// ---------------------------------------------------------------------------
// Transposes (unchanged from R2 — ~60us total, not on the critical path)
// ---------------------------------------------------------------------------
__global__ void t_in(const float* __restrict__ x)
{
    __shared__ float t[32][33];
    const int bh = blockIdx.z;
    const int b = bh >> 7, h = bh & 127;
    const int w0 = blockIdx.x * 32;
    const int c0 = blockIdx.y * 32;
    const int tx = threadIdx.x, ty = threadIdx.y;

    const float* src = x + (((size_t)b * 128 + c0) * 128 + h) * 128 + w0;
    #pragma unroll
    for (int i = 0; i < 4; ++i) {
        int c = ty * 4 + i;
        t[c][tx] = src[(size_t)c * 128 * 128 + tx];
    }
    __syncthreads();
    float* d = g_ws1 + (((size_t)b * 128 + h) * 128 + w0) * 128 + c0;
    #pragma unroll
    for (int i = 0; i < 4; ++i) {
        int w = ty * 4 + i;
        d[(size_t)w * 128 + tx] = t[tx][w];
    }
}

__global__ void t_mid()
{
    const int b = blockIdx.z;
    const int h = blockIdx.y;
    const int w = blockIdx.x * blockDim.y + threadIdx.y;
    const int c4 = threadIdx.x;
    const float4* s = (const float4*)(g_ws1 + (((size_t)b * 128 + h) * 128 + w) * 128);
    float4* d = (float4*)(g_ws2 + (((size_t)b * 128 + w) * 128 + h) * 128);
    d[c4] = s[c4];
}

__global__ void t_out(float* __restrict__ out)
{
    __shared__ float t[32][33];
    const int bh = blockIdx.z;
    const int b = bh >> 7, h = bh & 127;
    const int w0 = blockIdx.x * 32;
    const int c0 = blockIdx.y * 32;
    const int tx = threadIdx.x, ty = threadIdx.y;

    const float* src = g_ws2 + (((size_t)b * 128 + w0) * 128 + h) * 128 + c0;
    #pragma unroll
    for (int i = 0; i < 4; ++i) {
        int w = ty * 4 + i;
        t[w][tx] = src[(size_t)w * 128 * 128 + tx];
    }
    __syncthreads();
    float* d = out + (((size_t)b * 128 + c0) * 128 + h) * 128 + w0;
    #pragma unroll
    for (int i = 0; i < 4; ++i) {
        int c = ty * 4 + i;
        d[(size_t)c * 128 * 128 + tx] = t[tx][c];
    }
}

// ---------------------------------------------------------------------------
// Launch
// ---------------------------------------------------------------------------
extern "C" void kernel_launch(void* const* d_in, const int* in_sizes, int n_in,
                              void* d_out, int out_size)
{
    const float* x    = (const float*)d_in[0];
    const float* k_td = (const float*)d_in[1];
    const float* k_dt = (const float*)d_in[2];
    const float* k_lr = (const float*)d_in[3];
    const float* k_rl = (const float*)d_in[4];
    float* out = (float*)d_out;

    const dim3 tb(32, 8);
    const dim3 tg(4, 4, BB * HH);
    const dim3 sg(WW / MT, 128 / NT, BB);   // (4, 8, 8) = 256 blocks

    // (B,C,H,W) -> ws1 (B,H,W,C)
    t_in<<<tg, tb>>>(x);

    // top-down then bottom-up scans over H (conv over W)
    for (int s = 1; s < HH; ++s)
        step_kernel<0><<<sg, 256>>>(k_td, s, s - 1);
    for (int s = HH - 2; s >= 0; --s)
        step_kernel<0><<<sg, 256>>>(k_dt, s, s + 1);

    // ws1 (B,H,W,C) -> ws2 (B,W,H,C)
    t_mid<<<dim3(32, 128, BB), dim3(32, 4)>>>();

    // left-right then right-left scans over W (conv over H)
    for (int s = 1; s < WW; ++s)
        step_kernel<1><<<sg, 256>>>(k_lr, s, s - 1);
    for (int s = WW - 2; s >= 0; --s)
        step_kernel<1><<<sg, 256>>>(k_rl, s, s + 1);

    // ws2 (B,W,H,C) -> out (B,C,H,W)
    t_out<<<tg, tb>>>(out);
}

// round 4
// speedup vs baseline: 2.2684x; 1.0323x over previous
#include <cuda_runtime.h>

#define BB 8
#define HH 128
#define WW 128

// Workspaces: (B, S, P, C) with C contiguous. 64 MB each.
__device__ float g_ws1[(size_t)BB * HH * WW * 128];
__device__ float g_ws2[(size_t)BB * HH * WW * 128];

typedef unsigned long long ull;

#define MT 32      // positions per block
#define NT 32      // out-channels per block
#define AROW 129   // A row stride (odd => conflict-free strided row access)
#define NROWS 40   // MT + 8 halo rows

// ---------------------------------------------------------------------------
// One directional-scan step:
//   y[b,s_cur,p,oc] += relu( sum_{kw,ic} y[b,s_prev,p+kw-4,ic] * W9[kw,ic,oc] )
// Grid: 128 blocks (4 wtile x 4 octile x 8 batch) -> ONE wave on 148 SMs.
// Block: 256 threads = 8 warps, 8-way K-split (warp w -> ic [16w,16w+16)).
// Every warp computes the full 32pos x 32oc tile over its ic slice.
// Lane micro-tile: 4 pos x 8 oc, f32x2 packed accumulators (16 FFMA2/ic).
// Log2 cross-warp reduction through smem, epilogue by warp 0.
// ---------------------------------------------------------------------------
template <int WS>
__global__ __launch_bounds__(256) void step_kernel(const float* __restrict__ W9,
                                                   int s_cur, int s_prev)
{
    float* y = WS ? g_ws2 : g_ws1;

    __shared__ __align__(16) float Bs[128 * NT];       // 16KB  W9[kw] slice
    __shared__ __align__(16) float As[NROWS * AROW];   // 20.6KB window (Rs aliases)

    const int tid  = threadIdx.x;
    const int wid  = tid >> 5;       // 0..7  -> ic slice
    const int lane = tid & 31;
    const int pg   = lane >> 2;      // 0..7 -> positions 4pg..4pg+3
    const int og   = lane & 3;       // 0..3 -> oc 8og..8og+7
    const int ic0  = wid * 16;
    const int p0   = blockIdx.x * MT;
    const int oc0  = blockIdx.y * NT;
    const int b    = blockIdx.z;

    const float* prev = y + (((size_t)b * 128 + s_prev) * 128) * 128;

    // ---- Stage A window (rows p0-4 .. p0+35, zero-padded) ----
    #pragma unroll
    for (int q = 0; q < 5; ++q) {
        int idx = tid + 256 * q;        // 1280 float4s
        int r = idx >> 5, j = idx & 31;
        int gp = p0 - 4 + r;
        float4 v = make_float4(0.f, 0.f, 0.f, 0.f);
        if (gp >= 0 && gp < 128) v = *(const float4*)(prev + (size_t)gp * 128 + j * 4);
        float* d = &As[r * AROW + j * 4];
        d[0] = v.x; d[1] = v.y; d[2] = v.z; d[3] = v.w;
    }

    // ---- Stage B[kw=0]: 128ic x 32oc = 16KB, 4 float4 per thread ----
    const float* wbase = W9 + oc0;
    float4 wreg[4];
    #pragma unroll
    for (int q = 0; q < 4; ++q) {
        int j = tid + 256 * q;
        wreg[q] = *(const float4*)(wbase + (size_t)(j >> 3) * 128 + (j & 7) * 4);
    }
    #pragma unroll
    for (int q = 0; q < 4; ++q)
        *(float4*)&Bs[(tid + 256 * q) * 4] = wreg[q];
    __syncthreads();

    ull acc[4][4];
    #pragma unroll
    for (int p = 0; p < 4; ++p)
        #pragma unroll
        for (int q = 0; q < 4; ++q) acc[p][q] = 0ull;

    for (int kw = 0; kw < 9; ++kw) {
        // Prefetch next kw's weights into registers (LDG overlaps compute).
        if (kw < 8) {
            const float* wk = wbase + (size_t)(kw + 1) * 16384;
            #pragma unroll
            for (int q = 0; q < 4; ++q) {
                int j = tid + 256 * q;
                wreg[q] = *(const float4*)(wk + (size_t)(j >> 3) * 128 + (j & 7) * 4);
            }
        }

        const float* Ar = &As[(4 * pg + kw) * AROW + ic0];
        const float* Bp = &Bs[ic0 * NT + 8 * og];

        #pragma unroll
        for (int i = 0; i < 16; ++i) {
            float a0 = Ar[i];
            float a1 = Ar[i + AROW];
            float a2 = Ar[i + 2 * AROW];
            float a3 = Ar[i + 3 * AROW];
            ull d0, d1, d2, d3;
            asm("mov.b64 %0, {%1, %1};" : "=l"(d0) : "f"(a0));
            asm("mov.b64 %0, {%1, %1};" : "=l"(d1) : "f"(a1));
            asm("mov.b64 %0, {%1, %1};" : "=l"(d2) : "f"(a2));
            asm("mov.b64 %0, {%1, %1};" : "=l"(d3) : "f"(a3));
            ulonglong2 bx = *(const ulonglong2*)(Bp + i * NT);      // oc 0..3
            ulonglong2 by = *(const ulonglong2*)(Bp + i * NT + 4);  // oc 4..7
            asm("fma.rn.f32x2 %0, %1, %2, %0;" : "+l"(acc[0][0]) : "l"(d0), "l"(bx.x));
            asm("fma.rn.f32x2 %0, %1, %2, %0;" : "+l"(acc[0][1]) : "l"(d0), "l"(bx.y));
            asm("fma.rn.f32x2 %0, %1, %2, %0;" : "+l"(acc[0][2]) : "l"(d0), "l"(by.x));
            asm("fma.rn.f32x2 %0, %1, %2, %0;" : "+l"(acc[0][3]) : "l"(d0), "l"(by.y));
            asm("fma.rn.f32x2 %0, %1, %2, %0;" : "+l"(acc[1][0]) : "l"(d1), "l"(bx.x));
            asm("fma.rn.f32x2 %0, %1, %2, %0;" : "+l"(acc[1][1]) : "l"(d1), "l"(bx.y));
            asm("fma.rn.f32x2 %0, %1, %2, %0;" : "+l"(acc[1][2]) : "l"(d1), "l"(by.x));
            asm("fma.rn.f32x2 %0, %1, %2, %0;" : "+l"(acc[1][3]) : "l"(d1), "l"(by.y));
            asm("fma.rn.f32x2 %0, %1, %2, %0;" : "+l"(acc[2][0]) : "l"(d2), "l"(bx.x));
            asm("fma.rn.f32x2 %0, %1, %2, %0;" : "+l"(acc[2][1]) : "l"(d2), "l"(bx.y));
            asm("fma.rn.f32x2 %0, %1, %2, %0;" : "+l"(acc[2][2]) : "l"(d2), "l"(by.x));
            asm("fma.rn.f32x2 %0, %1, %2, %0;" : "+l"(acc[2][3]) : "l"(d2), "l"(by.y));
            asm("fma.rn.f32x2 %0, %1, %2, %0;" : "+l"(acc[3][0]) : "l"(d3), "l"(bx.x));
            asm("fma.rn.f32x2 %0, %1, %2, %0;" : "+l"(acc[3][1]) : "l"(d3), "l"(bx.y));
            asm("fma.rn.f32x2 %0, %1, %2, %0;" : "+l"(acc[3][2]) : "l"(d3), "l"(by.x));
            asm("fma.rn.f32x2 %0, %1, %2, %0;" : "+l"(acc[3][3]) : "l"(d3), "l"(by.y));
        }

        __syncthreads();                 // all warps done reading Bs
        if (kw < 8) {
            #pragma unroll
            for (int q = 0; q < 4; ++q)
                *(float4*)&Bs[(tid + 256 * q) * 4] = wreg[q];
        }
        __syncthreads();
    }

    // ---- Log2 cross-warp reduction. Rs aliases As (needs <= 16KB live). ----
    // Layout: Rs[slot][pq][lane] — element-major so each warp-wide ull
    // store/load hits 32 consecutive banks (conflict-free).
    float* Rs = As;

    auto dump = [&](int slot) {
        float* base = Rs + slot * 1024 + lane * 2;
        #pragma unroll
        for (int p = 0; p < 4; ++p)
            #pragma unroll
            for (int q = 0; q < 4; ++q)
                *(ull*)(base + (p * 4 + q) * 64) = acc[p][q];
    };
    auto gather = [&](int slot) {
        const float* base = Rs + slot * 1024 + lane * 2;
        #pragma unroll
        for (int p = 0; p < 4; ++p)
            #pragma unroll
            for (int q = 0; q < 4; ++q) {
                ull v = *(const ull*)(base + (p * 4 + q) * 64);
                asm("add.rn.f32x2 %0, %0, %1;" : "+l"(acc[p][q]) : "l"(v));
            }
    };

    if (wid >= 4) dump(wid - 4);
    __syncthreads();
    if (wid < 4) gather(wid);
    __syncthreads();
    if (wid == 2 || wid == 3) dump(wid - 2);
    __syncthreads();
    if (wid < 2) gather(wid);
    __syncthreads();
    if (wid == 1) dump(0);
    __syncthreads();

    if (wid == 0) {
        gather(0);
        // Epilogue: lane owns 4 pos x 8 oc. RMW + relu.
        #pragma unroll
        for (int p = 0; p < 4; ++p) {
            int pos = p0 + 4 * pg + p;
            float* dst = y + (((size_t)b * 128 + s_cur) * 128 + pos) * 128 + oc0 + 8 * og;
            float r0, r1, r2, r3, r4, r5, r6, r7;
            asm("mov.b64 {%0, %1}, %2;" : "=f"(r0), "=f"(r1) : "l"(acc[p][0]));
            asm("mov.b64 {%0, %1}, %2;" : "=f"(r2), "=f"(r3) : "l"(acc[p][1]));
            asm("mov.b64 {%0, %1}, %2;" : "=f"(r4), "=f"(r5) : "l"(acc[p][2]));
            asm("mov.b64 {%0, %1}, %2;" : "=f"(r6), "=f"(r7) : "l"(acc[p][3]));
            float4 c0 = *(float4*)dst;
            float4 c1 = *(float4*)(dst + 4);
            c0.x += fmaxf(r0, 0.f); c0.y += fmaxf(r1, 0.f);
            c0.z += fmaxf(r2, 0.f); c0.w += fmaxf(r3, 0.f);
            c1.x += fmaxf(r4, 0.f); c1.y += fmaxf(r5, 0.f);
            c1.z += fmaxf(r6, 0.f); c1.w += fmaxf(r7, 0.f);
            *(float4*)dst = c0;
            *(float4*)(dst + 4) = c1;
        }
    }
}

// ---------------------------------------------------------------------------
// Transposes (not on the critical path)
// ---------------------------------------------------------------------------
__global__ void t_in(const float* __restrict__ x)
{
    __shared__ float t[32][33];
    const int bh = blockIdx.z;
    const int b = bh >> 7, h = bh & 127;
    const int w0 = blockIdx.x * 32;
    const int c0 = blockIdx.y * 32;
    const int tx = threadIdx.x, ty = threadIdx.y;

    const float* src = x + (((size_t)b * 128 + c0) * 128 + h) * 128 + w0;
    #pragma unroll
    for (int i = 0; i < 4; ++i) {
        int c = ty * 4 + i;
        t[c][tx] = src[(size_t)c * 128 * 128 + tx];
    }
    __syncthreads();
    float* d = g_ws1 + (((size_t)b * 128 + h) * 128 + w0) * 128 + c0;
    #pragma unroll
    for (int i = 0; i < 4; ++i) {
        int w = ty * 4 + i;
        d[(size_t)w * 128 + tx] = t[tx][w];
    }
}

__global__ void t_mid()
{
    const int b = blockIdx.z;
    const int h = blockIdx.y;
    const int w = blockIdx.x * blockDim.y + threadIdx.y;
    const int c4 = threadIdx.x;
    const float4* s = (const float4*)(g_ws1 + (((size_t)b * 128 + h) * 128 + w) * 128);
    float4* d = (float4*)(g_ws2 + (((size_t)b * 128 + w) * 128 + h) * 128);
    d[c4] = s[c4];
}

__global__ void t_out(float* __restrict__ out)
{
    __shared__ float t[32][33];
    const int bh = blockIdx.z;
    const int b = bh >> 7, h = bh & 127;
    const int w0 = blockIdx.x * 32;
    const int c0 = blockIdx.y * 32;
    const int tx = threadIdx.x, ty = threadIdx.y;

    const float* src = g_ws2 + (((size_t)b * 128 + w0) * 128 + h) * 128 + c0;
    #pragma unroll
    for (int i = 0; i < 4; ++i) {
        int w = ty * 4 + i;
        t[w][tx] = src[(size_t)w * 128 * 128 + tx];
    }
    __syncthreads();
    float* d = out + (((size_t)b * 128 + c0) * 128 + h) * 128 + w0;
    #pragma unroll
    for (int i = 0; i < 4; ++i) {
        int c = ty * 4 + i;
        d[(size_t)c * 128 * 128 + tx] = t[tx][c];
    }
}

// ---------------------------------------------------------------------------
// Launch
// ---------------------------------------------------------------------------
extern "C" void kernel_launch(void* const* d_in, const int* in_sizes, int n_in,
                              void* d_out, int out_size)
{
    const float* x    = (const float*)d_in[0];
    const float* k_td = (const float*)d_in[1];
    const float* k_dt = (const float*)d_in[2];
    const float* k_lr = (const float*)d_in[3];
    const float* k_rl = (const float*)d_in[4];
    float* out = (float*)d_out;

    const dim3 tb(32, 8);
    const dim3 tg(4, 4, BB * HH);
    const dim3 sg(WW / MT, 128 / NT, BB);   // (4, 4, 8) = 128 blocks: ONE wave

    t_in<<<tg, tb>>>(x);

    for (int s = 1; s < HH; ++s)
        step_kernel<0><<<sg, 256>>>(k_td, s, s - 1);
    for (int s = HH - 2; s >= 0; --s)
        step_kernel<0><<<sg, 256>>>(k_dt, s, s + 1);

    t_mid<<<dim3(32, 128, BB), dim3(32, 4)>>>();

    for (int s = 1; s < WW; ++s)
        step_kernel<1><<<sg, 256>>>(k_lr, s, s - 1);
    for (int s = WW - 2; s >= 0; --s)
        step_kernel<1><<<sg, 256>>>(k_rl, s, s + 1);

    t_out<<<tg, tb>>>(out);
}